// round 1
// baseline (speedup 1.0000x reference)
#include <cuda_runtime.h>

#define BB 4
#define SS 256
#define HH 128
#define NR 40
#define TI 8
#define NT 512

// shared layout (float offsets)
#define O_QW  0            // 40*128 = 5120  (phase C: vw table)
#define O_KW  5120         // 5120
#define O_REL 10240        // 5120
#define O_Q   15360        // 256*128 = 32768 (phase C: value)
#define O_E1  48128        // 8*256 ints (rel_idx[b,j,i] transposed)
#define O_E2  50176        // 8*256 ints (rel_idx[b,i,j])
#define O_S   52224        // 8*256 scores -> exp weights
#define O_INV 54272        // 8 inv-sums
#define SMEM_FLOATS 54280
#define SMEM_BYTES  (SMEM_FLOATS * 4)

// accurate-enough tanh: 1 - 2/(e^{2x}+1)
// __expf: MUFU.EX2, rel err ~2^-22; __fdividef: MUFU.RCP + FMUL.
// Saturates correctly for |x| large (e->inf => 1; e->0 => -1).
__device__ __forceinline__ float fast_tanh(float x) {
    float e = __expf(x + x);
    return 1.0f - __fdividef(2.0f, e + 1.0f);
}

__global__ void __launch_bounds__(NT, 1)
rgat_kernel(const float* __restrict__ query, const float* __restrict__ key,
            const float* __restrict__ value, const float* __restrict__ rel_emb,
            const float* __restrict__ qw_emb, const float* __restrict__ kw_emb,
            const float* __restrict__ vw_emb, const int* __restrict__ src_len,
            const int* __restrict__ rel_idx, float* __restrict__ out)
{
    extern __shared__ float sm[];
    float* sh_qw  = sm + O_QW;
    float* sh_kw  = sm + O_KW;
    float* sh_rel = sm + O_REL;
    float* sh_q   = sm + O_Q;
    int*   sh_e1  = (int*)(sm + O_E1);
    int*   sh_e2  = (int*)(sm + O_E2);
    float* sh_s   = sm + O_S;
    float* sh_inv = sm + O_INV;

    const int tid = threadIdx.x;
    const int b  = blockIdx.x / (SS / TI);
    const int i0 = (blockIdx.x % (SS / TI)) * TI;
    const int srclen = src_len[b];

    const int TBL = NR * HH; // 5120

    // ---- stage tables (qw, kw, rel) ----
    for (int k = tid * 4; k < TBL; k += NT * 4) {
        *(float4*)(sh_qw  + k) = *(const float4*)(qw_emb  + k);
        *(float4*)(sh_kw  + k) = *(const float4*)(kw_emb  + k);
        *(float4*)(sh_rel + k) = *(const float4*)(rel_emb + k);
    }
    // ---- stage full query[b] ----
    const float* qb = query + b * SS * HH;
    for (int k = tid * 4; k < SS * HH; k += NT * 4)
        *(float4*)(sh_q + k) = *(const float4*)(qb + k);

    // ---- stage e1 = rel_idx[b, j, i0+ii]  (transpose on the fly) ----
    {
        int j = tid >> 1;
        int c = (tid & 1) * 4;
        int4 v = *(const int4*)(rel_idx + ((size_t)b * SS + j) * SS + i0 + c);
        sh_e1[(c + 0) * SS + j] = v.x;
        sh_e1[(c + 1) * SS + j] = v.y;
        sh_e1[(c + 2) * SS + j] = v.z;
        sh_e1[(c + 3) * SS + j] = v.w;
    }
    // ---- stage e2 = rel_idx[b, i0+ii, j] (8 contiguous rows) ----
    {
        int idx = tid * 4;           // 0..2044
        int ii  = idx >> 8;          // row within tile
        int j   = idx & (SS - 1);
        *(int4*)(sh_e2 + ii * SS + j) =
            *(const int4*)(rel_idx + ((size_t)b * SS + i0 + ii) * SS + j);
    }
    __syncthreads();

    const int w    = tid >> 5;
    const int lane = tid & 31;

    // ================= Phase A: scores =================
    // warp w -> row i = w/2, j parity = w&1 (interleaved for src_len balance)
    {
        const int i    = w >> 1;
        const int jpar = w & 1;
        const float4 k4 = *(const float4*)(key + ((size_t)b * SS + i0 + i) * HH + lane * 4);

        for (int jj = 0; jj < SS / 2; jj++) {
            const int j = jpar + (jj << 1);
            float sv = -1e18f;
            if (j < srclen) {                       // warp-uniform branch
                const int e1 = sh_e1[i * SS + j];
                const int e2 = sh_e2[i * SS + j];
                const float4 q  = *(float4*)(sh_q   + j  * HH + lane * 4);
                const float4 qw = *(float4*)(sh_qw  + e1 * HH + lane * 4);
                const float4 kw = *(float4*)(sh_kw  + e2 * HH + lane * 4);
                const float4 r  = *(float4*)(sh_rel + e1 * HH + lane * 4);

                float t0 = fast_tanh(fmaf(qw.x, q.x, kw.x * k4.x));
                float t1 = fast_tanh(fmaf(qw.y, q.y, kw.y * k4.y));
                float t2 = fast_tanh(fmaf(qw.z, q.z, kw.z * k4.z));
                float t3 = fast_tanh(fmaf(qw.w, q.w, kw.w * k4.w));

                float acc = r.x * t0;
                acc = fmaf(r.y, t1, acc);
                acc = fmaf(r.z, t2, acc);
                acc = fmaf(r.w, t3, acc);

                acc += __shfl_xor_sync(0xffffffffu, acc, 16);
                acc += __shfl_xor_sync(0xffffffffu, acc, 8);
                acc += __shfl_xor_sync(0xffffffffu, acc, 4);
                acc += __shfl_xor_sync(0xffffffffu, acc, 2);
                acc += __shfl_xor_sync(0xffffffffu, acc, 1);
                sv = acc;
            }
            if (lane == 0) sh_s[i * SS + j] = sv;
        }
    }
    __syncthreads();

    // ---- restage value[b] over sh_q, vw table over sh_qw (reads done) ----
    const float* vb = value + b * SS * HH;
    for (int k = tid * 4; k < SS * HH; k += NT * 4)
        *(float4*)(sh_q + k) = *(const float4*)(vb + k);
    for (int k = tid * 4; k < TBL; k += NT * 4)
        *(float4*)(sh_qw + k) = *(const float4*)(vw_emb + k);

    // ================= Phase B: softmax (warps 0..7 own one row each) =========
    if (w < TI) {
        float vals[8];
        float m = -3.0e38f;
        #pragma unroll
        for (int k = 0; k < 8; k++) {
            vals[k] = sh_s[w * SS + lane + k * 32];
            m = fmaxf(m, vals[k]);
        }
        #pragma unroll
        for (int o = 16; o; o >>= 1) m = fmaxf(m, __shfl_xor_sync(0xffffffffu, m, o));
        float ssum = 0.0f;
        #pragma unroll
        for (int k = 0; k < 8; k++) {
            float e = __expf(vals[k] - m);   // masked entries -> exp(-huge) = 0
            sh_s[w * SS + lane + k * 32] = e;
            ssum += e;
        }
        #pragma unroll
        for (int o = 16; o; o >>= 1) ssum += __shfl_xor_sync(0xffffffffu, ssum, o);
        if (lane == 0) sh_inv[w] = 1.0f / ssum;
    }
    __syncthreads();

    // ================= Phase C: output =================
    // thread -> (row ci, h-pair). per warp: ci uniform, e1/att broadcast,
    // vw/value LDS.64 conflict-free.
    {
        const int ci = tid >> 6;            // 0..7
        const int hh = (tid & 63) * 2;      // h offset (float2)
        float ax = 0.0f, ay = 0.0f;
        for (int j = 0; j < srclen; j++) {
            const float a  = sh_s[ci * SS + j];
            const int   e1 = sh_e1[ci * SS + j];
            const float2 vw = *(float2*)(sh_qw + e1 * HH + hh);
            const float2 vv = *(float2*)(sh_q  + j  * HH + hh);
            ax = fmaf(a * vw.x, vv.x, ax);
            ay = fmaf(a * vw.y, vv.y, ay);
        }
        const float inv = sh_inv[ci];
        float2 o;
        o.x = ax * inv;
        o.y = ay * inv;
        *(float2*)(out + ((size_t)b * SS + i0 + ci) * HH + hh) = o;
    }
}

extern "C" void kernel_launch(void* const* d_in, const int* in_sizes, int n_in,
                              void* d_out, int out_size) {
    const float* query   = (const float*)d_in[0];
    const float* key_t   = (const float*)d_in[1];
    const float* value   = (const float*)d_in[2];
    const float* rel_emb = (const float*)d_in[3];
    const float* qw_emb  = (const float*)d_in[4];
    const float* kw_emb  = (const float*)d_in[5];
    const float* vw_emb  = (const float*)d_in[6];
    const int*   src_len = (const int*)d_in[7];
    const int*   rel_idx = (const int*)d_in[8];
    float* out = (float*)d_out;

    cudaFuncSetAttribute(rgat_kernel,
                         cudaFuncAttributeMaxDynamicSharedMemorySize, SMEM_BYTES);

    rgat_kernel<<<BB * (SS / TI), NT, SMEM_BYTES>>>(
        query, key_t, value, rel_emb, qw_emb, kw_emb, vw_emb,
        src_len, rel_idx, out);
}

// round 2
// speedup vs baseline: 1.3217x; 1.3217x over previous
#include <cuda_runtime.h>

#define BB 4
#define SS 256
#define HH 128
#define NR 40
#define TI 8
#define NT 1024

// shared layout (float offsets)
#define O_QW  0            // 40*128 = 5120  (phase C: vw table)
#define O_KW  5120         // 5120
#define O_REL 10240        // 5120
#define O_Q   15360        // 256*128 = 32768 (phase C: value)
#define O_E1  48128        // 8*256 ints (rel_idx[b,j,i] transposed)
#define O_E2  50176        // 8*256 ints (rel_idx[b,i,j])
#define O_S   52224        // 8*256 scores -> exp weights
#define O_INV 54272        // 8 inv-sums
#define SMEM_FLOATS 54280
#define SMEM_BYTES  (SMEM_FLOATS * 4)

// accurate tanh: 1 - 2/(e^{2x}+1)   (MUFU.EX2 + MUFU.RCP, rel err ~1e-6)
__device__ __forceinline__ float fast_tanh(float x) {
    float e = __expf(x + x);
    return 1.0f - __fdividef(2.0f, e + 1.0f);
}

__global__ void __launch_bounds__(NT, 1)
rgat_kernel(const float* __restrict__ query, const float* __restrict__ key,
            const float* __restrict__ value, const float* __restrict__ rel_emb,
            const float* __restrict__ qw_emb, const float* __restrict__ kw_emb,
            const float* __restrict__ vw_emb, const int* __restrict__ src_len,
            const int* __restrict__ rel_idx, float* __restrict__ out)
{
    extern __shared__ float sm[];
    float* sh_qw  = sm + O_QW;
    float* sh_kw  = sm + O_KW;
    float* sh_rel = sm + O_REL;
    float* sh_q   = sm + O_Q;
    int*   sh_e1  = (int*)(sm + O_E1);
    int*   sh_e2  = (int*)(sm + O_E2);
    float* sh_s   = sm + O_S;
    float* sh_inv = sm + O_INV;

    const int tid = threadIdx.x;
    const int b  = blockIdx.x / (SS / TI);
    const int i0 = (blockIdx.x % (SS / TI)) * TI;
    const int srclen = src_len[b];

    const int TBL = NR * HH; // 5120

    // ---- stage tables (qw, kw, rel) ----
    for (int k = tid * 4; k < TBL; k += NT * 4) {
        *(float4*)(sh_qw  + k) = *(const float4*)(qw_emb  + k);
        *(float4*)(sh_kw  + k) = *(const float4*)(kw_emb  + k);
        *(float4*)(sh_rel + k) = *(const float4*)(rel_emb + k);
    }
    // ---- stage full query[b] ----
    const float* qb = query + b * SS * HH;
    for (int k = tid * 4; k < SS * HH; k += NT * 4)
        *(float4*)(sh_q + k) = *(const float4*)(qb + k);

    // ---- stage e1 = rel_idx[b, j, i0+ii] (transpose) and e2 = rel_idx[b, i0+ii, j] ----
    if (tid < 512) {
        int j = tid >> 1;
        int c = (tid & 1) * 4;
        int4 v = *(const int4*)(rel_idx + ((size_t)b * SS + j) * SS + i0 + c);
        sh_e1[(c + 0) * SS + j] = v.x;
        sh_e1[(c + 1) * SS + j] = v.y;
        sh_e1[(c + 2) * SS + j] = v.z;
        sh_e1[(c + 3) * SS + j] = v.w;

        int idx = tid * 4;           // 0..2044
        int ii  = idx >> 8;
        int jj  = idx & (SS - 1);
        *(int4*)(sh_e2 + ii * SS + jj) =
            *(const int4*)(rel_idx + ((size_t)b * SS + i0 + ii) * SS + jj);
    }
    __syncthreads();

    const int w    = tid >> 5;
    const int lane = tid & 31;

    // ================= Phase A: scores =================
    // 32 warps: warp -> (row iw = w>>2, j offset p = w&3). Within warp, four
    // 8-lane groups each own one j per iteration; lane covers 16 h values.
    {
        const int iw  = w >> 2;          // 0..7
        const int p   = w & 3;           // j mod 4
        const int g   = lane >> 3;       // group 0..3
        const int lig = lane & 7;        // lane in group

        const float* kb = key + ((size_t)b * SS + i0 + iw) * HH + lig * 4;
        const float4 kr0 = *(const float4*)(kb + 0);
        const float4 kr1 = *(const float4*)(kb + 32);
        const float4 kr2 = *(const float4*)(kb + 64);
        const float4 kr3 = *(const float4*)(kb + 96);

        #pragma unroll 2
        for (int jj = 0; jj < 16; jj++) {
            const int jb = p + (jj << 4);      // warp-uniform
            const int j  = jb + (g << 2);      // group's j
            if (jb >= srclen) {                // warp-uniform: all 4 groups invalid
                if (lig == 0) sh_s[iw * SS + j] = -1e18f;
                continue;
            }
            const int e1 = sh_e1[iw * SS + j];
            const int e2 = sh_e2[iw * SS + j];
            const float* qp  = sh_q   + j  * HH + lig * 4;
            const float* qwp = sh_qw  + e1 * HH + lig * 4;
            const float* kwp = sh_kw  + e2 * HH + lig * 4;
            const float* rp  = sh_rel + e1 * HH + lig * 4;

            float a0 = 0.0f, a1 = 0.0f, a2 = 0.0f, a3 = 0.0f;
#define ASTEP(KR, OFF, ACC) { \
            const float4 q  = *(const float4*)(qp  + OFF); \
            const float4 qw = *(const float4*)(qwp + OFF); \
            const float4 kw = *(const float4*)(kwp + OFF); \
            const float4 r  = *(const float4*)(rp  + OFF); \
            ACC = fmaf(r.x, fast_tanh(fmaf(qw.x, q.x, kw.x * KR.x)), ACC); \
            ACC = fmaf(r.y, fast_tanh(fmaf(qw.y, q.y, kw.y * KR.y)), ACC); \
            ACC = fmaf(r.z, fast_tanh(fmaf(qw.z, q.z, kw.z * KR.z)), ACC); \
            ACC = fmaf(r.w, fast_tanh(fmaf(qw.w, q.w, kw.w * KR.w)), ACC); }
            ASTEP(kr0,  0, a0)
            ASTEP(kr1, 32, a1)
            ASTEP(kr2, 64, a2)
            ASTEP(kr3, 96, a3)
#undef ASTEP
            float acc = (a0 + a1) + (a2 + a3);
            acc += __shfl_xor_sync(0xffffffffu, acc, 4);
            acc += __shfl_xor_sync(0xffffffffu, acc, 2);
            acc += __shfl_xor_sync(0xffffffffu, acc, 1);
            if (lig == 0)
                sh_s[iw * SS + j] = (j < srclen) ? acc : -1e18f;
        }
    }
    __syncthreads();

    // ---- restage value[b] over sh_q, vw table over sh_qw (reads done) ----
    const float* vb = value + b * SS * HH;
    for (int k = tid * 4; k < SS * HH; k += NT * 4)
        *(float4*)(sh_q + k) = *(const float4*)(vb + k);
    for (int k = tid * 4; k < TBL; k += NT * 4)
        *(float4*)(sh_qw + k) = *(const float4*)(vw_emb + k);

    // ================= Phase B: softmax (warps 0..7, one row each) =========
    if (w < TI) {
        float vals[8];
        float m = -3.0e38f;
        #pragma unroll
        for (int k = 0; k < 8; k++) {
            vals[k] = sh_s[w * SS + lane + k * 32];
            m = fmaxf(m, vals[k]);
        }
        #pragma unroll
        for (int o = 16; o; o >>= 1) m = fmaxf(m, __shfl_xor_sync(0xffffffffu, m, o));
        float ssum = 0.0f;
        #pragma unroll
        for (int k = 0; k < 8; k++) {
            float e = __expf(vals[k] - m);   // masked -> 0
            sh_s[w * SS + lane + k * 32] = e;
            ssum += e;
        }
        #pragma unroll
        for (int o = 16; o; o >>= 1) ssum += __shfl_xor_sync(0xffffffffu, ssum, o);
        if (lane == 0) sh_inv[w] = 1.0f / ssum;
    }
    __syncthreads();

    // ================= Phase C: output =================
    // thread -> (row ci, scalar h). a/e1 warp-uniform broadcast; vw/value
    // consecutive-float LDS, conflict-free.
    {
        const int ci = tid >> 7;            // 0..7
        const int h  = tid & (HH - 1);      // 0..127
        float acc = 0.0f;
        #pragma unroll 4
        for (int j = 0; j < srclen; j++) {
            const float a  = sh_s[ci * SS + j];
            const int   e1 = sh_e1[ci * SS + j];
            acc = fmaf(a * sh_qw[e1 * HH + h], sh_q[j * HH + h], acc);
        }
        out[((size_t)b * SS + i0 + ci) * HH + h] = acc * sh_inv[ci];
    }
}

extern "C" void kernel_launch(void* const* d_in, const int* in_sizes, int n_in,
                              void* d_out, int out_size) {
    const float* query   = (const float*)d_in[0];
    const float* key_t   = (const float*)d_in[1];
    const float* value   = (const float*)d_in[2];
    const float* rel_emb = (const float*)d_in[3];
    const float* qw_emb  = (const float*)d_in[4];
    const float* kw_emb  = (const float*)d_in[5];
    const float* vw_emb  = (const float*)d_in[6];
    const int*   src_len = (const int*)d_in[7];
    const int*   rel_idx = (const int*)d_in[8];
    float* out = (float*)d_out;

    cudaFuncSetAttribute(rgat_kernel,
                         cudaFuncAttributeMaxDynamicSharedMemorySize, SMEM_BYTES);

    rgat_kernel<<<BB * (SS / TI), NT, SMEM_BYTES>>>(
        query, key_t, value, rel_emb, qw_emb, kw_emb, vw_emb,
        src_len, rel_idx, out);
}